// round 16
// baseline (speedup 1.0000x reference)
#include <cuda_runtime.h>
#include <cuda_fp16.h>
#include <mma.h>

using namespace nvcuda;

// ---------------- problem constants ----------------
#define UN  100000
#define INC 50000
#define NN  150000
#define DD  64
#define KK  128
#define EE  1250000
#define LL  2

typedef unsigned long long u64;

// ---------------- device scratch (static; no allocations) ----------------
__device__ __half g_ekhA[NN * DD];    // e0 (layer0 in), preserved through layer1
__device__ __half g_ekhB[NN * DD];    // e1 (layer1 in)
__device__ int   g_cnt[NN];           // zeroed by apply_scan of PREVIOUS call (BSS-zero first call)
__device__ int   g_rowptr[NN + 1];
__device__ int   g_wp[NN];
__device__ int2  g_edge[EE];          // {tail, adj-as-int} in CSR order
// packed normalized vectors: per node 16 chunks of 16B; chunk c = {gnn̂[4c..4c+3], itl̂[4c..4c+3]} fp16
__device__ __half g_nrm[NN * 128];
__device__ float g_normg[NN];         // |gnn| per node
__device__ float g_normi[NN];         // |itl| per node
__device__ int   g_bsum[160];
__device__ int   g_boff[160];
__device__ int   g_done;              // reset by reduce_scan's last block (BSS-zero first call)
__device__ int   g_dbin[256];         // degree histogram (reset by deg_scan; BSS-zero first call)
__device__ int   g_dwp[256];
__device__ int   g_perm[NN];          // degree-sorted node permutation

// ---------------- fused init_ek ∥ hist (disjoint writes; block-split) ----------------
#define NB_INIT (NN * DD / 4 / 256)        // 9375
#define NB_HIST ((EE / 4 + 255) / 256)     // 1221

__global__ void init_hist_kernel(const float4* __restrict__ ue, const float4* __restrict__ ie,
                                 const int4* __restrict__ h4) {
    int bx = blockIdx.x;
    if (bx < NB_INIT) {
        int i = bx * 256 + threadIdx.x;
        const int UD4 = UN * DD / 4;
        float4 v = (i < UD4) ? ue[i] : ie[i - UD4];
        __half2 h0 = __floats2half2_rn(v.x, v.y);
        __half2 h1 = __floats2half2_rn(v.z, v.w);
        uint2 u; u.x = *(unsigned*)&h0; u.y = *(unsigned*)&h1;
        ((uint2*)g_ekhA)[i] = u;
    } else {
        int i = (bx - NB_INIT) * 256 + threadIdx.x;
        if (i >= EE / 4) return;
        int4 v = __ldg(h4 + i);
        atomicAdd(&g_cnt[v.x], 1);
        atomicAdd(&g_cnt[v.y], 1);
        atomicAdd(&g_cnt[v.z], 1);
        atomicAdd(&g_cnt[v.w], 1);
    }
}

__global__ void reduce_scan_kernel() {
    __shared__ int s[1024];
    __shared__ bool amLast;
    int tid = threadIdx.x;
    int idx = blockIdx.x * 1024 + tid;
    s[tid] = (idx < NN) ? g_cnt[idx] : 0;
    __syncthreads();
    for (int o = 512; o > 0; o >>= 1) {
        if (tid < o) s[tid] += s[tid + o];
        __syncthreads();
    }
    if (tid == 0) {
        g_bsum[blockIdx.x] = s[0];
        __threadfence();
        amLast = (atomicAdd(&g_done, 1) == gridDim.x - 1);
    }
    __syncthreads();
    if (amLast) {
        int nblk = gridDim.x;
        int v = (tid < nblk) ? g_bsum[tid] : 0;
        s[tid] = v;
        __syncthreads();
        for (int off = 1; off < 1024; off <<= 1) {
            int t = (tid >= off) ? s[tid - off] : 0;
            __syncthreads();
            s[tid] += t;
            __syncthreads();
        }
        if (tid < nblk) g_boff[tid] = s[tid] - v;   // exclusive
        if (tid == 0) g_done = 0;                    // reset for next replay
    }
}

// rowptr/wp + cnt pre-zero + degree histogram (smem-aggregated)
__global__ void apply_scan_kernel() {
    __shared__ int s[1024];
    __shared__ int sb[256];
    int tid = threadIdx.x;
    int idx = blockIdx.x * 1024 + tid;
    int v = (idx < NN) ? g_cnt[idx] : 0;
    if (tid < 256) sb[tid] = 0;
    s[tid] = v;
    __syncthreads();
    for (int off = 1; off < 1024; off <<= 1) {
        int t = (tid >= off) ? s[tid - off] : 0;
        __syncthreads();
        s[tid] += t;
        __syncthreads();
    }
    int excl = s[tid] - v + g_boff[blockIdx.x];
    if (idx < NN) {
        g_rowptr[idx] = excl;
        g_wp[idx]     = excl;
        g_cnt[idx]    = 0;             // pre-zero for NEXT replay's hist
        int d = v > 255 ? 255 : v;
        atomicAdd(&sb[d], 1);
    }
    __syncthreads();
    if (tid < 256 && sb[tid]) atomicAdd(&g_dbin[tid], sb[tid]);
    if (blockIdx.x == 0 && tid == 0) g_rowptr[NN] = EE;
}

// 256-bin exclusive scan of degree histogram (1 block)
__global__ void deg_scan_kernel() {
    __shared__ int s[256];
    int tid = threadIdx.x;
    int v = g_dbin[tid];
    s[tid] = v;
    __syncthreads();
    for (int off = 1; off < 256; off <<= 1) {
        int t = (tid >= off) ? s[tid - off] : 0;
        __syncthreads();
        s[tid] += t;
        __syncthreads();
    }
    g_dwp[tid]  = s[tid] - v;          // exclusive
    g_dbin[tid] = 0;                   // reset for next replay
}

// edge scatter ∥ perm scatter (block-split)
#define NB_SCAT ((EE / 8 + 255) / 256)     // 611
#define NB_PERM ((NN + 255) / 256)         // 586

__global__ void scatter_kernel(const int4* __restrict__ h4, const int4* __restrict__ t4,
                               const float4* __restrict__ adj4) {
    int bx = blockIdx.x;
    if (bx < NB_SCAT) {
        int i = bx * 256 + threadIdx.x;    // 8 edges per thread
        if (i >= EE / 8) return;
        int4  hv0 = __ldg(h4 + 2 * i),   hv1 = __ldg(h4 + 2 * i + 1);
        int4  tv0 = __ldg(t4 + 2 * i),   tv1 = __ldg(t4 + 2 * i + 1);
        float4 av0 = __ldg(adj4 + 2 * i), av1 = __ldg(adj4 + 2 * i + 1);
        int p0 = atomicAdd(&g_wp[hv0.x], 1);
        int p1 = atomicAdd(&g_wp[hv0.y], 1);
        int p2 = atomicAdd(&g_wp[hv0.z], 1);
        int p3 = atomicAdd(&g_wp[hv0.w], 1);
        int p4 = atomicAdd(&g_wp[hv1.x], 1);
        int p5 = atomicAdd(&g_wp[hv1.y], 1);
        int p6 = atomicAdd(&g_wp[hv1.z], 1);
        int p7 = atomicAdd(&g_wp[hv1.w], 1);
        g_edge[p0] = make_int2(tv0.x, __float_as_int(av0.x));
        g_edge[p1] = make_int2(tv0.y, __float_as_int(av0.y));
        g_edge[p2] = make_int2(tv0.z, __float_as_int(av0.z));
        g_edge[p3] = make_int2(tv0.w, __float_as_int(av0.w));
        g_edge[p4] = make_int2(tv1.x, __float_as_int(av1.x));
        g_edge[p5] = make_int2(tv1.y, __float_as_int(av1.y));
        g_edge[p6] = make_int2(tv1.z, __float_as_int(av1.z));
        g_edge[p7] = make_int2(tv1.w, __float_as_int(av1.w));
    } else {
        int i = (bx - NB_SCAT) * 256 + threadIdx.x;
        if (i >= NN) return;
        int d = g_rowptr[i + 1] - g_rowptr[i];
        if (d > 255) d = 255;
        int p = atomicAdd(&g_dwp[d], 1);
        g_perm[p] = i;
    }
}

// ---------------- smem layout for tensor-core intent (TM=64) ----------------
#define TM 64
#define WH_LD 136
#define AH_LD 72
#define PH_LD 136
#define PS_LD 132
#define IT_SMEM_BYTES (17408 + 17408 + 33792)   // 68608

// ---------------- spmm body (16-lane group per node, degree-paired); gnn + gnn̂ + |gnn| ----------------
__device__ __forceinline__ void spmm_body(int layer, float* __restrict__ out, int bx) {
    const __half* __restrict__ ekhIn = layer ? g_ekhB : g_ekhA;
    const uint2* __restrict__ ekh2 = (const uint2*)ekhIn;
    int t0 = bx * 256 + threadIdx.x;
    int grp = t0 >> 4;
    int g = __ldg(g_perm + grp);
    int l = threadIdx.x & 15;
    unsigned m = 0xFFFFu << (threadIdx.x & 16);
    int s = g_rowptr[g], e = g_rowptr[g + 1];
    float4 acc = make_float4(0.f, 0.f, 0.f, 0.f);

    int p = s;
    for (; p + 3 < e; p += 4) {
        int2 e0 = __ldg(g_edge + p);
        int2 e1 = __ldg(g_edge + p + 1);
        int2 e2 = __ldg(g_edge + p + 2);
        int2 e3 = __ldg(g_edge + p + 3);
        uint2 x0 = ekh2[(size_t)e0.x * 16 + l];
        uint2 x1 = ekh2[(size_t)e1.x * 16 + l];
        uint2 x2 = ekh2[(size_t)e2.x * 16 + l];
        uint2 x3 = ekh2[(size_t)e3.x * 16 + l];
        float v0 = __int_as_float(e0.y), v1 = __int_as_float(e1.y);
        float v2 = __int_as_float(e2.y), v3 = __int_as_float(e3.y);
        float2 a01, a23;
        a01 = __half22float2(*(__half2*)&x0.x); a23 = __half22float2(*(__half2*)&x0.y);
        acc.x = fmaf(v0, a01.x, acc.x); acc.y = fmaf(v0, a01.y, acc.y);
        acc.z = fmaf(v0, a23.x, acc.z); acc.w = fmaf(v0, a23.y, acc.w);
        a01 = __half22float2(*(__half2*)&x1.x); a23 = __half22float2(*(__half2*)&x1.y);
        acc.x = fmaf(v1, a01.x, acc.x); acc.y = fmaf(v1, a01.y, acc.y);
        acc.z = fmaf(v1, a23.x, acc.z); acc.w = fmaf(v1, a23.y, acc.w);
        a01 = __half22float2(*(__half2*)&x2.x); a23 = __half22float2(*(__half2*)&x2.y);
        acc.x = fmaf(v2, a01.x, acc.x); acc.y = fmaf(v2, a01.y, acc.y);
        acc.z = fmaf(v2, a23.x, acc.z); acc.w = fmaf(v2, a23.y, acc.w);
        a01 = __half22float2(*(__half2*)&x3.x); a23 = __half22float2(*(__half2*)&x3.y);
        acc.x = fmaf(v3, a01.x, acc.x); acc.y = fmaf(v3, a01.y, acc.y);
        acc.z = fmaf(v3, a23.x, acc.z); acc.w = fmaf(v3, a23.y, acc.w);
    }
    for (; p < e; p++) {
        int2 e0 = __ldg(g_edge + p);
        uint2 x0 = ekh2[(size_t)e0.x * 16 + l];
        float v0 = __int_as_float(e0.y);
        float2 a01 = __half22float2(*(__half2*)&x0.x);
        float2 a23 = __half22float2(*(__half2*)&x0.y);
        acc.x = fmaf(v0, a01.x, acc.x); acc.y = fmaf(v0, a01.y, acc.y);
        acc.z = fmaf(v0, a23.x, acc.z); acc.w = fmaf(v0, a23.y, acc.w);
    }
    __stcs((float4*)(out + (size_t)g * DD + l * 4), acc);   // write-once: streaming
    float sg = acc.x * acc.x + acc.y * acc.y + acc.z * acc.z + acc.w * acc.w;
#pragma unroll
    for (int o = 8; o > 0; o >>= 1) sg += __shfl_xor_sync(m, sg, o);
    float rt  = fmaxf(sqrtf(sg), 1e-12f);
    float inv = 1.f / rt;
    if (l == 0) g_normg[g] = rt;
    __half2 h0 = __floats2half2_rn(acc.x * inv, acc.y * inv);
    __half2 h1 = __floats2half2_rn(acc.z * inv, acc.w * inv);
    uint2 u;
    u.x = *(unsigned*)&h0;
    u.y = *(unsigned*)&h1;
    ((uint2*)g_nrm)[(size_t)g * 32 + l * 2] = u;   // g-part of chunk l (hot: default policy)
}

// ---------------- intent body (tensor cores): softmax(ek@W)@W^T per 64-row tile ----------------
__device__ __forceinline__ void intent_body(int layer, const float* __restrict__ W,
                                            float* __restrict__ outIntl,
                                            int nodeBase, int nodeCount, int bx) {
    const __half* __restrict__ ekhIn = layer ? g_ekhB : g_ekhA;
    extern __shared__ char smc[];
    __half* Wh = (__half*)smc;                  // [64][136]
    __half* Ah = (__half*)(smc + 17408);        // [64][72]  (dead after GEMM1)
    __half* Ph = (__half*)(smc + 17408);        // [64][136] (overlays Ah)
    float*  Ps = (float*)(smc + 34816);         // [64][132]

    int tid = threadIdx.x;
    int warp = tid >> 5, lane = tid & 31;
    int rowTile = bx * TM;

    // load W (fp32 -> fp16) into Wh
#pragma unroll
    for (int it = 0; it < 8; it++) {
        int i = tid + it * 256;                  // float4 index
        float4 v = __ldg((const float4*)W + i);
        int d  = i >> 5;
        int k4 = (i & 31) * 4;
        __half2 h0 = __floats2half2_rn(v.x, v.y);
        __half2 h1 = __floats2half2_rn(v.z, v.w);
        uint2 u; u.x = *(unsigned*)&h0; u.y = *(unsigned*)&h1;
        *(uint2*)(Wh + d * WH_LD + k4) = u;
    }
    // load A rows from fp16 ek
    {
        int row = tid >> 2;
        int seg = tid & 3;
        uint4 z0 = make_uint4(0, 0, 0, 0), z1 = make_uint4(0, 0, 0, 0);
        int r = rowTile + row;
        if (r < nodeCount) {
            const uint4* src = (const uint4*)(ekhIn + (size_t)(nodeBase + r) * DD) + seg * 2;
            z0 = src[0]; z1 = src[1];
        }
        uint4* dst = (uint4*)(Ah + row * AH_LD + seg * 16);
        dst[0] = z0; dst[1] = z1;
    }
    __syncthreads();

    // GEMM1: logits[64][128] = A[64][64] @ W[64][128]
    {
        int wm = warp >> 1, wn = warp & 1;
        wmma::fragment<wmma::matrix_a, 16, 16, 16, __half, wmma::row_major> a[4];
#pragma unroll
        for (int kt = 0; kt < 4; kt++)
            wmma::load_matrix_sync(a[kt], Ah + wm * 16 * AH_LD + kt * 16, AH_LD);
#pragma unroll
        for (int nt = 0; nt < 4; nt++) {
            wmma::fragment<wmma::accumulator, 16, 16, 16, float> c;
            wmma::fill_fragment(c, 0.f);
#pragma unroll
            for (int kt = 0; kt < 4; kt++) {
                wmma::fragment<wmma::matrix_b, 16, 16, 16, __half, wmma::row_major> b;
                wmma::load_matrix_sync(b, Wh + kt * 16 * WH_LD + wn * 64 + nt * 16, WH_LD);
                wmma::mma_sync(c, a[kt], b, c);
            }
            wmma::store_matrix_sync(Ps + wm * 16 * PS_LD + wn * 64 + nt * 16, c, PS_LD,
                                    wmma::mem_row_major);
        }
    }
    __syncthreads();

    // row softmax on Ps (fp32), write probs fp16 to Ph
    for (int rr = warp; rr < TM; rr += 8) {
        float4 v = *(float4*)(Ps + rr * PS_LD + lane * 4);
        float mx = fmaxf(fmaxf(v.x, v.y), fmaxf(v.z, v.w));
#pragma unroll
        for (int o = 16; o > 0; o >>= 1) mx = fmaxf(mx, __shfl_xor_sync(0xffffffffu, mx, o));
        float e0 = __expf(v.x - mx), e1 = __expf(v.y - mx);
        float e2 = __expf(v.z - mx), e3 = __expf(v.w - mx);
        float sum = e0 + e1 + e2 + e3;
#pragma unroll
        for (int o = 16; o > 0; o >>= 1) sum += __shfl_xor_sync(0xffffffffu, sum, o);
        float inv = 1.0f / sum;
        __half2 h0 = __floats2half2_rn(e0 * inv, e1 * inv);
        __half2 h1 = __floats2half2_rn(e2 * inv, e3 * inv);
        uint2 u; u.x = *(unsigned*)&h0; u.y = *(unsigned*)&h1;
        *(uint2*)(Ph + rr * PH_LD + lane * 4) = u;
    }
    __syncthreads();

    // GEMM2: out[64][64] = P[64][128] @ W^T[128][64]  (kt-outer, a-fragment reused)
    {
        int wm = warp >> 1, wn = warp & 1;
        wmma::fragment<wmma::accumulator, 16, 16, 16, float> c[2];
        wmma::fill_fragment(c[0], 0.f);
        wmma::fill_fragment(c[1], 0.f);
#pragma unroll
        for (int kt = 0; kt < 8; kt++) {
            wmma::fragment<wmma::matrix_a, 16, 16, 16, __half, wmma::row_major> a;
            wmma::load_matrix_sync(a, Ph + wm * 16 * PH_LD + kt * 16, PH_LD);
#pragma unroll
            for (int nt = 0; nt < 2; nt++) {
                wmma::fragment<wmma::matrix_b, 16, 16, 16, __half, wmma::col_major> b;
                wmma::load_matrix_sync(b, Wh + (wn * 32 + nt * 16) * WH_LD + kt * 16, WH_LD);
                wmma::mma_sync(c[nt], a, b, c[nt]);
            }
        }
#pragma unroll
        for (int nt = 0; nt < 2; nt++)
            wmma::store_matrix_sync(Ps + wm * 16 * PS_LD + wn * 32 + nt * 16, c[nt], PS_LD,
                                    wmma::mem_row_major);
    }
    __syncthreads();

    // epilogue: store itl (fp32, streaming) + row norms + g_nrm i-part (fp16)
    for (int rr = warp; rr < TM; rr += 8) {
        float2 v = *(float2*)(Ps + rr * PS_LD + lane * 2);
        float ns = v.x * v.x + v.y * v.y;
#pragma unroll
        for (int o = 16; o > 0; o >>= 1) ns += __shfl_xor_sync(0xffffffffu, ns, o);
        float rt  = fmaxf(sqrtf(ns), 1e-12f);
        float inv = 1.f / rt;
        __half2 hv = __floats2half2_rn(v.x * inv, v.y * inv);
        unsigned lo = *(unsigned*)&hv;
        unsigned hi = __shfl_down_sync(0xffffffffu, lo, 1);
        int r = rowTile + rr;
        if (r < nodeCount) {
            __stcs((float2*)(outIntl + (size_t)(nodeBase + r) * DD + lane * 2), v);
            if (lane == 0) g_normi[nodeBase + r] = rt;
            if ((lane & 1) == 0) {
                uint2 u; u.x = lo; u.y = hi;
                ((uint2*)g_nrm)[(size_t)(nodeBase + r) * 32 + (lane >> 1) * 2 + 1] = u;
            }
        }
    }
}

// ---------------- merged phase-1 kernel: interleaved intent/spmm dispatch ----------------
#define NB_IU ((UN + TM - 1) / TM)      // 1563
#define NB_II ((INC + TM - 1) / TM)     // 782
#define NB_I  (NB_IU + NB_II)           // 2345
#define NB_SP (NN * 16 / 256)           // 9375

__global__ void __launch_bounds__(256)
phase1_kernel(int layer, const float* __restrict__ Wu, const float* __restrict__ Wi,
              float* __restrict__ gnn, float* __restrict__ itl) {
    int bx = blockIdx.x;
    int k = bx >> 2;
    if ((bx & 3) == 0 && k < NB_I) {
        if (k < NB_IU) intent_body(layer, Wu, itl, 0, UN, k);
        else           intent_body(layer, Wi, itl, UN, INC, k - NB_IU);
    } else {
        int before = (bx >> 2) + 1;
        if (before > NB_I) before = NB_I;
        spmm_body(layer, gnn, bx - before);
    }
}

// ---------------- fused alpha + spmm2 + combine (16-lane group per node, degree-paired) ----------------
#define EDGE_DOT_P(na_, dd_)                                                  \
    {                                                                         \
        __half2 pg = __hfma2(hgy, *(__half2*)&(na_).y,                        \
                             __hmul2(hgx, *(__half2*)&(na_).x));              \
        __half2 pi = __hfma2(hiy, *(__half2*)&(na_).w,                        \
                             __hmul2(hix, *(__half2*)&(na_).z));              \
        dd_ = __halves2half2(__hadd(__low2half(pg), __high2half(pg)),         \
                             __hadd(__low2half(pi), __high2half(pi)));        \
    }

#define H2SHFL(dd_, o_)                                                       \
    {                                                                         \
        unsigned _w = *(unsigned*)&(dd_);                                     \
        unsigned _r = __shfl_xor_sync(m, _w, o_);                             \
        dd_ = __hadd2(dd_, *(__half2*)&_r);                                   \
    }

#define EDGE_ACC(ea_, a_g, a_i)                                               \
    {                                                                         \
        float2 k01 = __half22float2(*(__half2*)&(ea_).x);                     \
        float2 k23 = __half22float2(*(__half2*)&(ea_).y);                     \
        AG.x = fmaf(a_g, k01.x, AG.x); AG.y = fmaf(a_g, k01.y, AG.y);         \
        AG.z = fmaf(a_g, k23.x, AG.z); AG.w = fmaf(a_g, k23.y, AG.w);         \
        AI.x = fmaf(a_i, k01.x, AI.x); AI.y = fmaf(a_i, k01.y, AI.y);         \
        AI.z = fmaf(a_i, k23.x, AI.z); AI.w = fmaf(a_i, k23.y, AI.w);         \
        rsg += a_g; rsi += a_i;                                               \
    }

__global__ void __launch_bounds__(256)
fused_alpha_kernel(int layer,
                   float* __restrict__ gaa, float* __restrict__ iaa,
                   float* __restrict__ finalOut) {
    const __half* __restrict__ ekhIn  = layer ? g_ekhB : g_ekhA;
    __half*       __restrict__ ekhOut = layer ? g_ekhA : g_ekhB;
    int t0 = blockIdx.x * blockDim.x + threadIdx.x;
    int grp = t0 >> 4;
    int g = __ldg(g_perm + grp);
    int l = threadIdx.x & 15;
    unsigned m = 0xFFFFu << (threadIdx.x & 16);
    size_t ro = (size_t)g * DD + l * 4;
    const uint4* __restrict__ nrm4 = (const uint4*)g_nrm;
    const uint2* __restrict__ ekh2 = (const uint2*)ekhIn;

    uint4 hn = nrm4[(size_t)g * 16 + l];
    __half2 hgx = *(__half2*)&hn.x, hgy = *(__half2*)&hn.y;
    __half2 hix = *(__half2*)&hn.z, hiy = *(__half2*)&hn.w;
    float ng = g_normg[g], ni = g_normi[g];

    float4 AG = make_float4(0.f, 0.f, 0.f, 0.f);
    float4 AI = make_float4(0.f, 0.f, 0.f, 0.f);
    float rsg = 0.f, rsi = 0.f;

    int s = g_rowptr[g], e = g_rowptr[g + 1];
    int p = s;
    for (; p + 3 < e; p += 4) {
        int ta = __ldg(&g_edge[p].x);
        int tb = __ldg(&g_edge[p + 1].x);
        int tc = __ldg(&g_edge[p + 2].x);
        int td = __ldg(&g_edge[p + 3].x);
        uint4 na = nrm4[(size_t)ta * 16 + l];
        uint4 nb = nrm4[(size_t)tb * 16 + l];
        uint4 nc = nrm4[(size_t)tc * 16 + l];
        uint4 nd = nrm4[(size_t)td * 16 + l];
        uint2 ea = ekh2[(size_t)ta * 16 + l];
        uint2 eb = ekh2[(size_t)tb * 16 + l];
        uint2 ec = ekh2[(size_t)tc * 16 + l];
        uint2 ed = ekh2[(size_t)td * 16 + l];

        __half2 dda, ddb, ddc, ddd;
        EDGE_DOT_P(na, dda);
        EDGE_DOT_P(nb, ddb);
        EDGE_DOT_P(nc, ddc);
        EDGE_DOT_P(nd, ddd);
#pragma unroll
        for (int o = 8; o > 0; o >>= 1) {
            H2SHFL(dda, o);
            H2SHFL(ddb, o);
            H2SHFL(ddc, o);
            H2SHFL(ddd, o);
        }
        float2 dfa = __half22float2(dda);
        float2 dfb = __half22float2(ddb);
        float2 dfc = __half22float2(ddc);
        float2 dfd = __half22float2(ddd);
        float aga = (dfa.x + 1.f) * 0.5f, aia = (dfa.y + 1.f) * 0.5f;
        float agb = (dfb.x + 1.f) * 0.5f, aib = (dfb.y + 1.f) * 0.5f;
        float agc = (dfc.x + 1.f) * 0.5f, aic = (dfc.y + 1.f) * 0.5f;
        float agd = (dfd.x + 1.f) * 0.5f, aid = (dfd.y + 1.f) * 0.5f;
        EDGE_ACC(ea, aga, aia);
        EDGE_ACC(eb, agb, aib);
        EDGE_ACC(ec, agc, aic);
        EDGE_ACC(ed, agd, aid);
    }
    for (; p < e; p++) {
        int ta = __ldg(&g_edge[p].x);
        uint4 na = nrm4[(size_t)ta * 16 + l];
        uint2 ea = ekh2[(size_t)ta * 16 + l];
        __half2 dda;
        EDGE_DOT_P(na, dda);
#pragma unroll
        for (int o = 8; o > 0; o >>= 1) H2SHFL(dda, o);
        float2 dfa = __half22float2(dda);
        float aga = (dfa.x + 1.f) * 0.5f, aia = (dfa.y + 1.f) * 0.5f;
        EDGE_ACC(ea, aga, aia);
    }
    float dg_inv = rsg > 0.f ? 1.f / rsg : 0.f;
    float di_inv = rsi > 0.f ? 1.f / rsi : 0.f;
    float4 gv = make_float4(AG.x * dg_inv, AG.y * dg_inv, AG.z * dg_inv, AG.w * dg_inv);
    float4 iv = make_float4(AI.x * di_inv, AI.y * di_inv, AI.z * di_inv, AI.w * di_inv);
    __stcs((float4*)(gaa + ro), gv);     // write-once: streaming
    __stcs((float4*)(iaa + ro), iv);

    // combine: e_{l+1} = gnn + intl + gaa + iaa + ek
    // gnn/itl rows reconstructed from registers: |gnn|·ĝ, |itl|·î
    float2 hg01 = __half22float2(hgx), hg23 = __half22float2(hgy);
    float2 hi01 = __half22float2(hix), hi23 = __half22float2(hiy);
    uint2 ekc = ekh2[(size_t)g * 16 + l];
    float2 ek01 = __half22float2(*(__half2*)&ekc.x);
    float2 ek23 = __half22float2(*(__half2*)&ekc.y);
    float4 en;
    en.x = fmaf(ng, hg01.x, fmaf(ni, hi01.x, gv.x + iv.x + ek01.x));
    en.y = fmaf(ng, hg01.y, fmaf(ni, hi01.y, gv.y + iv.y + ek01.y));
    en.z = fmaf(ng, hg23.x, fmaf(ni, hi23.x, gv.z + iv.z + ek23.x));
    en.w = fmaf(ng, hg23.y, fmaf(ni, hi23.y, gv.w + iv.w + ek23.y));
    if (finalOut) {
        // final = e0 + e1 + e2 ; e0 lives in g_ekhA, e1 = ekhIn (=g_ekhB)
        uint2 e0c = ((const uint2*)g_ekhA)[(size_t)g * 16 + l];
        float2 z01 = __half22float2(*(__half2*)&e0c.x);
        float2 z23 = __half22float2(*(__half2*)&e0c.y);
        float4 ac;
        ac.x = z01.x + ek01.x + en.x;
        ac.y = z01.y + ek01.y + en.y;
        ac.z = z23.x + ek23.x + en.z;
        ac.w = z23.y + ek23.y + en.w;
        __stcs((float4*)(finalOut + ro), ac);   // write-once: streaming
    } else {
        __half2 h0 = __floats2half2_rn(en.x, en.y);
        __half2 h1 = __floats2half2_rn(en.z, en.w);
        uint2 u; u.x = *(unsigned*)&h0; u.y = *(unsigned*)&h1;
        ((uint2*)ekhOut)[(size_t)g * 16 + l] = u;   // hot: default policy
    }
}

// ---------------- launch ----------------
extern "C" void kernel_launch(void* const* d_in, const int* in_sizes, int n_in,
                              void* d_out, int out_size) {
    const float* user_emb = (const float*)d_in[0];
    const float* item_emb = (const float*)d_in[1];
    const float* Wu       = (const float*)d_in[2];
    const float* Wi       = (const float*)d_in[3];
    const float* adj      = (const float*)d_in[4];
    const int*   h        = (const int*)d_in[5];
    const int*   t        = (const int*)d_in[6];
    (void)in_sizes; (void)n_in; (void)out_size;

    float* out = (float*)d_out;
    const size_t ND = (size_t)NN * DD;
    float* out_ua  = out;                    // [N*D] = ua | ia
    float* out_gnn = out + ND;               // [L][N][D]
    float* out_int = out_gnn + (size_t)LL * ND;
    float* out_gaa = out_int + (size_t)LL * ND;
    float* out_iaa = out_gaa + (size_t)LL * ND;

    cudaFuncSetAttribute(phase1_kernel, cudaFuncAttributeMaxDynamicSharedMemorySize, IT_SMEM_BYTES);

    const int TPB = 256;
    const int SCAN_NB = (NN + 1023) / 1024;  // 147
    init_hist_kernel<<<NB_INIT + NB_HIST, TPB>>>((const float4*)user_emb,
                                                 (const float4*)item_emb,
                                                 (const int4*)h);
    reduce_scan_kernel<<<SCAN_NB, 1024>>>();
    apply_scan_kernel<<<SCAN_NB, 1024>>>();
    deg_scan_kernel<<<1, 256>>>();
    scatter_kernel<<<NB_SCAT + NB_PERM, TPB>>>((const int4*)h, (const int4*)t,
                                               (const float4*)adj);

    const int NODE_BLOCKS = NN * 16 / TPB;   // 9375
    for (int l = 0; l < LL; l++) {
        float* gnn = out_gnn + (size_t)l * ND;
        float* itl = out_int + (size_t)l * ND;
        float* gaa = out_gaa + (size_t)l * ND;
        float* iaa = out_iaa + (size_t)l * ND;

        phase1_kernel<<<NB_I + NB_SP, TPB, IT_SMEM_BYTES>>>(l, Wu, Wi, gnn, itl);
        fused_alpha_kernel<<<NODE_BLOCKS, TPB>>>(l, gaa, iaa,
                                                 (l == LL - 1) ? out_ua : nullptr);
    }
}

// round 17
// speedup vs baseline: 1.0801x; 1.0801x over previous
#include <cuda_runtime.h>
#include <cuda_fp16.h>
#include <mma.h>

using namespace nvcuda;

// ---------------- problem constants ----------------
#define UN  100000
#define INC 50000
#define NN  150000
#define DD  64
#define KK  128
#define EE  1250000
#define LL  2

typedef unsigned long long u64;

// ---------------- device scratch (static; no allocations) ----------------
__device__ __half g_ekhA[NN * DD];    // e0 (layer0 in), preserved through layer1
__device__ __half g_ekhB[NN * DD];    // e1 (layer1 in)
__device__ int   g_cnt[NN];           // zeroed by apply_scan of PREVIOUS call (BSS-zero first call)
__device__ int   g_rowptr[NN + 1];
__device__ int   g_wp[NN];
__device__ int2  g_edge[EE];          // {tail, adj-as-int} in CSR order
// packed normalized vectors: per node 16 chunks of 16B; chunk c = {gnn̂[4c..4c+3], itl̂[4c..4c+3]} fp16
__device__ __half g_nrm[NN * 128];
__device__ float g_normg[NN];         // |gnn| per node
__device__ float g_normi[NN];         // |itl| per node
__device__ int   g_bsum[160];
__device__ int   g_boff[160];
__device__ int   g_done;              // reset by reduce_scan's last block (BSS-zero first call)

// ---------------- fused init_ek ∥ hist (disjoint writes; block-split) ----------------
#define NB_INIT (NN * DD / 4 / 256)        // 9375
#define NB_HIST ((EE / 4 + 255) / 256)     // 1221

__global__ void init_hist_kernel(const float4* __restrict__ ue, const float4* __restrict__ ie,
                                 const int4* __restrict__ h4) {
    int bx = blockIdx.x;
    if (bx < NB_INIT) {
        int i = bx * 256 + threadIdx.x;
        const int UD4 = UN * DD / 4;
        float4 v = (i < UD4) ? ue[i] : ie[i - UD4];
        __half2 h0 = __floats2half2_rn(v.x, v.y);
        __half2 h1 = __floats2half2_rn(v.z, v.w);
        uint2 u; u.x = *(unsigned*)&h0; u.y = *(unsigned*)&h1;
        ((uint2*)g_ekhA)[i] = u;
    } else {
        int i = (bx - NB_INIT) * 256 + threadIdx.x;
        if (i >= EE / 4) return;
        int4 v = __ldg(h4 + i);
        atomicAdd(&g_cnt[v.x], 1);
        atomicAdd(&g_cnt[v.y], 1);
        atomicAdd(&g_cnt[v.z], 1);
        atomicAdd(&g_cnt[v.w], 1);
    }
}

__global__ void reduce_scan_kernel() {
    __shared__ int s[1024];
    __shared__ bool amLast;
    int tid = threadIdx.x;
    int idx = blockIdx.x * 1024 + tid;
    s[tid] = (idx < NN) ? g_cnt[idx] : 0;
    __syncthreads();
    for (int o = 512; o > 0; o >>= 1) {
        if (tid < o) s[tid] += s[tid + o];
        __syncthreads();
    }
    if (tid == 0) {
        g_bsum[blockIdx.x] = s[0];
        __threadfence();
        amLast = (atomicAdd(&g_done, 1) == gridDim.x - 1);
    }
    __syncthreads();
    if (amLast) {
        int nblk = gridDim.x;
        int v = (tid < nblk) ? g_bsum[tid] : 0;
        s[tid] = v;
        __syncthreads();
        for (int off = 1; off < 1024; off <<= 1) {
            int t = (tid >= off) ? s[tid - off] : 0;
            __syncthreads();
            s[tid] += t;
            __syncthreads();
        }
        if (tid < nblk) g_boff[tid] = s[tid] - v;   // exclusive
        if (tid == 0) g_done = 0;                    // reset for next replay
    }
}

__global__ void apply_scan_kernel() {
    __shared__ int s[1024];
    int tid = threadIdx.x;
    int idx = blockIdx.x * 1024 + tid;
    int v = (idx < NN) ? g_cnt[idx] : 0;
    s[tid] = v;
    __syncthreads();
    for (int off = 1; off < 1024; off <<= 1) {
        int t = (tid >= off) ? s[tid - off] : 0;
        __syncthreads();
        s[tid] += t;
        __syncthreads();
    }
    int excl = s[tid] - v + g_boff[blockIdx.x];
    if (idx < NN) {
        g_rowptr[idx] = excl;
        g_wp[idx]     = excl;
        g_cnt[idx]    = 0;             // pre-zero for NEXT replay's hist
    }
    if (blockIdx.x == 0 && tid == 0) g_rowptr[NN] = EE;
}

__global__ void scatter_kernel(const int4* __restrict__ h4, const int4* __restrict__ t4,
                               const float4* __restrict__ adj4) {
    int i = blockIdx.x * blockDim.x + threadIdx.x;    // 8 edges per thread
    if (i >= EE / 8) return;
    int4  hv0 = __ldg(h4 + 2 * i),   hv1 = __ldg(h4 + 2 * i + 1);
    int4  tv0 = __ldg(t4 + 2 * i),   tv1 = __ldg(t4 + 2 * i + 1);
    float4 av0 = __ldg(adj4 + 2 * i), av1 = __ldg(adj4 + 2 * i + 1);
    int p0 = atomicAdd(&g_wp[hv0.x], 1);
    int p1 = atomicAdd(&g_wp[hv0.y], 1);
    int p2 = atomicAdd(&g_wp[hv0.z], 1);
    int p3 = atomicAdd(&g_wp[hv0.w], 1);
    int p4 = atomicAdd(&g_wp[hv1.x], 1);
    int p5 = atomicAdd(&g_wp[hv1.y], 1);
    int p6 = atomicAdd(&g_wp[hv1.z], 1);
    int p7 = atomicAdd(&g_wp[hv1.w], 1);
    g_edge[p0] = make_int2(tv0.x, __float_as_int(av0.x));
    g_edge[p1] = make_int2(tv0.y, __float_as_int(av0.y));
    g_edge[p2] = make_int2(tv0.z, __float_as_int(av0.z));
    g_edge[p3] = make_int2(tv0.w, __float_as_int(av0.w));
    g_edge[p4] = make_int2(tv1.x, __float_as_int(av1.x));
    g_edge[p5] = make_int2(tv1.y, __float_as_int(av1.y));
    g_edge[p6] = make_int2(tv1.z, __float_as_int(av1.z));
    g_edge[p7] = make_int2(tv1.w, __float_as_int(av1.w));
}

// ---------------- smem layout for tensor-core intent (TM=64) ----------------
#define TM 64
#define WH_LD 136
#define AH_LD 72
#define PH_LD 136
#define PS_LD 132
#define IT_SMEM_BYTES (17408 + 17408 + 33792)   // 68608

// ---------------- spmm body (16-lane group per node); fp16 gathers; gnn + gnn̂ + |gnn| ----------------
__device__ __forceinline__ void spmm_body(int layer, float* __restrict__ out, int bx) {
    const __half* __restrict__ ekhIn = layer ? g_ekhB : g_ekhA;
    const uint2* __restrict__ ekh2 = (const uint2*)ekhIn;
    int t0 = bx * 256 + threadIdx.x;
    int g = t0 >> 4;
    int l = threadIdx.x & 15;
    unsigned m = 0xFFFFu << (threadIdx.x & 16);
    int s = g_rowptr[g], e = g_rowptr[g + 1];
    float4 acc = make_float4(0.f, 0.f, 0.f, 0.f);

    int p = s;
    for (; p + 3 < e; p += 4) {
        int2 e0 = __ldg(g_edge + p);
        int2 e1 = __ldg(g_edge + p + 1);
        int2 e2 = __ldg(g_edge + p + 2);
        int2 e3 = __ldg(g_edge + p + 3);
        uint2 x0 = ekh2[(size_t)e0.x * 16 + l];
        uint2 x1 = ekh2[(size_t)e1.x * 16 + l];
        uint2 x2 = ekh2[(size_t)e2.x * 16 + l];
        uint2 x3 = ekh2[(size_t)e3.x * 16 + l];
        float v0 = __int_as_float(e0.y), v1 = __int_as_float(e1.y);
        float v2 = __int_as_float(e2.y), v3 = __int_as_float(e3.y);
        float2 a01, a23;
        a01 = __half22float2(*(__half2*)&x0.x); a23 = __half22float2(*(__half2*)&x0.y);
        acc.x = fmaf(v0, a01.x, acc.x); acc.y = fmaf(v0, a01.y, acc.y);
        acc.z = fmaf(v0, a23.x, acc.z); acc.w = fmaf(v0, a23.y, acc.w);
        a01 = __half22float2(*(__half2*)&x1.x); a23 = __half22float2(*(__half2*)&x1.y);
        acc.x = fmaf(v1, a01.x, acc.x); acc.y = fmaf(v1, a01.y, acc.y);
        acc.z = fmaf(v1, a23.x, acc.z); acc.w = fmaf(v1, a23.y, acc.w);
        a01 = __half22float2(*(__half2*)&x2.x); a23 = __half22float2(*(__half2*)&x2.y);
        acc.x = fmaf(v2, a01.x, acc.x); acc.y = fmaf(v2, a01.y, acc.y);
        acc.z = fmaf(v2, a23.x, acc.z); acc.w = fmaf(v2, a23.y, acc.w);
        a01 = __half22float2(*(__half2*)&x3.x); a23 = __half22float2(*(__half2*)&x3.y);
        acc.x = fmaf(v3, a01.x, acc.x); acc.y = fmaf(v3, a01.y, acc.y);
        acc.z = fmaf(v3, a23.x, acc.z); acc.w = fmaf(v3, a23.y, acc.w);
    }
    for (; p < e; p++) {
        int2 e0 = __ldg(g_edge + p);
        uint2 x0 = ekh2[(size_t)e0.x * 16 + l];
        float v0 = __int_as_float(e0.y);
        float2 a01 = __half22float2(*(__half2*)&x0.x);
        float2 a23 = __half22float2(*(__half2*)&x0.y);
        acc.x = fmaf(v0, a01.x, acc.x); acc.y = fmaf(v0, a01.y, acc.y);
        acc.z = fmaf(v0, a23.x, acc.z); acc.w = fmaf(v0, a23.y, acc.w);
    }
    __stcs((float4*)(out + (size_t)g * DD + l * 4), acc);   // write-once: streaming
    float sg = acc.x * acc.x + acc.y * acc.y + acc.z * acc.z + acc.w * acc.w;
#pragma unroll
    for (int o = 8; o > 0; o >>= 1) sg += __shfl_xor_sync(m, sg, o);
    float rt  = fmaxf(sqrtf(sg), 1e-12f);
    float inv = 1.f / rt;
    if (l == 0) g_normg[g] = rt;
    __half2 h0 = __floats2half2_rn(acc.x * inv, acc.y * inv);
    __half2 h1 = __floats2half2_rn(acc.z * inv, acc.w * inv);
    uint2 u;
    u.x = *(unsigned*)&h0;
    u.y = *(unsigned*)&h1;
    ((uint2*)g_nrm)[(size_t)g * 32 + l * 2] = u;   // g-part of chunk l (hot: default policy)
}

// ---------------- intent body (tensor cores): softmax(ek@W)@W^T per 64-row tile ----------------
__device__ __forceinline__ void intent_body(int layer, const float* __restrict__ W,
                                            float* __restrict__ outIntl,
                                            int nodeBase, int nodeCount, int bx) {
    const __half* __restrict__ ekhIn = layer ? g_ekhB : g_ekhA;
    extern __shared__ char smc[];
    __half* Wh = (__half*)smc;                  // [64][136]
    __half* Ah = (__half*)(smc + 17408);        // [64][72]  (dead after GEMM1)
    __half* Ph = (__half*)(smc + 17408);        // [64][136] (overlays Ah)
    float*  Ps = (float*)(smc + 34816);         // [64][132]

    int tid = threadIdx.x;
    int warp = tid >> 5, lane = tid & 31;
    int rowTile = bx * TM;

    // load W (fp32 -> fp16) into Wh
#pragma unroll
    for (int it = 0; it < 8; it++) {
        int i = tid + it * 256;                  // float4 index
        float4 v = __ldg((const float4*)W + i);
        int d  = i >> 5;
        int k4 = (i & 31) * 4;
        __half2 h0 = __floats2half2_rn(v.x, v.y);
        __half2 h1 = __floats2half2_rn(v.z, v.w);
        uint2 u; u.x = *(unsigned*)&h0; u.y = *(unsigned*)&h1;
        *(uint2*)(Wh + d * WH_LD + k4) = u;
    }
    // load A rows from fp16 ek
    {
        int row = tid >> 2;
        int seg = tid & 3;
        uint4 z0 = make_uint4(0, 0, 0, 0), z1 = make_uint4(0, 0, 0, 0);
        int r = rowTile + row;
        if (r < nodeCount) {
            const uint4* src = (const uint4*)(ekhIn + (size_t)(nodeBase + r) * DD) + seg * 2;
            z0 = src[0]; z1 = src[1];
        }
        uint4* dst = (uint4*)(Ah + row * AH_LD + seg * 16);
        dst[0] = z0; dst[1] = z1;
    }
    __syncthreads();

    // GEMM1: logits[64][128] = A[64][64] @ W[64][128]
    {
        int wm = warp >> 1, wn = warp & 1;
        wmma::fragment<wmma::matrix_a, 16, 16, 16, __half, wmma::row_major> a[4];
#pragma unroll
        for (int kt = 0; kt < 4; kt++)
            wmma::load_matrix_sync(a[kt], Ah + wm * 16 * AH_LD + kt * 16, AH_LD);
#pragma unroll
        for (int nt = 0; nt < 4; nt++) {
            wmma::fragment<wmma::accumulator, 16, 16, 16, float> c;
            wmma::fill_fragment(c, 0.f);
#pragma unroll
            for (int kt = 0; kt < 4; kt++) {
                wmma::fragment<wmma::matrix_b, 16, 16, 16, __half, wmma::row_major> b;
                wmma::load_matrix_sync(b, Wh + kt * 16 * WH_LD + wn * 64 + nt * 16, WH_LD);
                wmma::mma_sync(c, a[kt], b, c);
            }
            wmma::store_matrix_sync(Ps + wm * 16 * PS_LD + wn * 64 + nt * 16, c, PS_LD,
                                    wmma::mem_row_major);
        }
    }
    __syncthreads();

    // row softmax on Ps (fp32), write probs fp16 to Ph
    for (int rr = warp; rr < TM; rr += 8) {
        float4 v = *(float4*)(Ps + rr * PS_LD + lane * 4);
        float mx = fmaxf(fmaxf(v.x, v.y), fmaxf(v.z, v.w));
#pragma unroll
        for (int o = 16; o > 0; o >>= 1) mx = fmaxf(mx, __shfl_xor_sync(0xffffffffu, mx, o));
        float e0 = __expf(v.x - mx), e1 = __expf(v.y - mx);
        float e2 = __expf(v.z - mx), e3 = __expf(v.w - mx);
        float sum = e0 + e1 + e2 + e3;
#pragma unroll
        for (int o = 16; o > 0; o >>= 1) sum += __shfl_xor_sync(0xffffffffu, sum, o);
        float inv = 1.0f / sum;
        __half2 h0 = __floats2half2_rn(e0 * inv, e1 * inv);
        __half2 h1 = __floats2half2_rn(e2 * inv, e3 * inv);
        uint2 u; u.x = *(unsigned*)&h0; u.y = *(unsigned*)&h1;
        *(uint2*)(Ph + rr * PH_LD + lane * 4) = u;
    }
    __syncthreads();

    // GEMM2: out[64][64] = P[64][128] @ W^T[128][64]  (kt-outer, a-fragment reused)
    {
        int wm = warp >> 1, wn = warp & 1;
        wmma::fragment<wmma::accumulator, 16, 16, 16, float> c[2];
        wmma::fill_fragment(c[0], 0.f);
        wmma::fill_fragment(c[1], 0.f);
#pragma unroll
        for (int kt = 0; kt < 8; kt++) {
            wmma::fragment<wmma::matrix_a, 16, 16, 16, __half, wmma::row_major> a;
            wmma::load_matrix_sync(a, Ph + wm * 16 * PH_LD + kt * 16, PH_LD);
#pragma unroll
            for (int nt = 0; nt < 2; nt++) {
                wmma::fragment<wmma::matrix_b, 16, 16, 16, __half, wmma::col_major> b;
                wmma::load_matrix_sync(b, Wh + (wn * 32 + nt * 16) * WH_LD + kt * 16, WH_LD);
                wmma::mma_sync(c[nt], a, b, c[nt]);
            }
        }
#pragma unroll
        for (int nt = 0; nt < 2; nt++)
            wmma::store_matrix_sync(Ps + wm * 16 * PS_LD + wn * 32 + nt * 16, c[nt], PS_LD,
                                    wmma::mem_row_major);
    }
    __syncthreads();

    // epilogue: store itl (fp32, streaming) + row norms + g_nrm i-part (fp16)
    for (int rr = warp; rr < TM; rr += 8) {
        float2 v = *(float2*)(Ps + rr * PS_LD + lane * 2);
        float ns = v.x * v.x + v.y * v.y;
#pragma unroll
        for (int o = 16; o > 0; o >>= 1) ns += __shfl_xor_sync(0xffffffffu, ns, o);
        float rt  = fmaxf(sqrtf(ns), 1e-12f);
        float inv = 1.f / rt;
        __half2 hv = __floats2half2_rn(v.x * inv, v.y * inv);
        unsigned lo = *(unsigned*)&hv;
        unsigned hi = __shfl_down_sync(0xffffffffu, lo, 1);
        int r = rowTile + rr;
        if (r < nodeCount) {
            __stcs((float2*)(outIntl + (size_t)(nodeBase + r) * DD + lane * 2), v);
            if (lane == 0) g_normi[nodeBase + r] = rt;
            if ((lane & 1) == 0) {
                uint2 u; u.x = lo; u.y = hi;
                ((uint2*)g_nrm)[(size_t)(nodeBase + r) * 32 + (lane >> 1) * 2 + 1] = u;
            }
        }
    }
}

// ---------------- merged phase-1 kernel: interleaved intent/spmm dispatch ----------------
#define NB_IU ((UN + TM - 1) / TM)      // 1563
#define NB_II ((INC + TM - 1) / TM)     // 782
#define NB_I  (NB_IU + NB_II)           // 2345
#define NB_SP (NN * 16 / 256)           // 9375

__global__ void __launch_bounds__(256)
phase1_kernel(int layer, const float* __restrict__ Wu, const float* __restrict__ Wi,
              float* __restrict__ gnn, float* __restrict__ itl) {
    int bx = blockIdx.x;
    int k = bx >> 2;
    if ((bx & 3) == 0 && k < NB_I) {
        if (k < NB_IU) intent_body(layer, Wu, itl, 0, UN, k);
        else           intent_body(layer, Wi, itl, UN, INC, k - NB_IU);
    } else {
        int before = (bx >> 2) + 1;
        if (before > NB_I) before = NB_I;
        spmm_body(layer, gnn, bx - before);
    }
}

// ---------------- fused alpha + spmm2 + combine (16-lane group per node) ----------------
#define EDGE_DOT_P(na_, dd_)                                                  \
    {                                                                         \
        __half2 pg = __hfma2(hgy, *(__half2*)&(na_).y,                        \
                             __hmul2(hgx, *(__half2*)&(na_).x));              \
        __half2 pi = __hfma2(hiy, *(__half2*)&(na_).w,                        \
                             __hmul2(hix, *(__half2*)&(na_).z));              \
        dd_ = __halves2half2(__hadd(__low2half(pg), __high2half(pg)),         \
                             __hadd(__low2half(pi), __high2half(pi)));        \
    }

#define H2SHFL(dd_, o_)                                                       \
    {                                                                         \
        unsigned _w = *(unsigned*)&(dd_);                                     \
        unsigned _r = __shfl_xor_sync(m, _w, o_);                             \
        dd_ = __hadd2(dd_, *(__half2*)&_r);                                   \
    }

#define EDGE_ACC(ea_, a_g, a_i)                                               \
    {                                                                         \
        float2 k01 = __half22float2(*(__half2*)&(ea_).x);                     \
        float2 k23 = __half22float2(*(__half2*)&(ea_).y);                     \
        AG.x = fmaf(a_g, k01.x, AG.x); AG.y = fmaf(a_g, k01.y, AG.y);         \
        AG.z = fmaf(a_g, k23.x, AG.z); AG.w = fmaf(a_g, k23.y, AG.w);         \
        AI.x = fmaf(a_i, k01.x, AI.x); AI.y = fmaf(a_i, k01.y, AI.y);         \
        AI.z = fmaf(a_i, k23.x, AI.z); AI.w = fmaf(a_i, k23.y, AI.w);         \
        rsg += a_g; rsi += a_i;                                               \
    }

__global__ void __launch_bounds__(256)
fused_alpha_kernel(int layer,
                   float* __restrict__ gaa, float* __restrict__ iaa,
                   float* __restrict__ finalOut) {
    const __half* __restrict__ ekhIn  = layer ? g_ekhB : g_ekhA;
    __half*       __restrict__ ekhOut = layer ? g_ekhA : g_ekhB;
    int t0 = blockIdx.x * blockDim.x + threadIdx.x;
    int g = t0 >> 4;
    int l = threadIdx.x & 15;
    unsigned m = 0xFFFFu << (threadIdx.x & 16);
    size_t ro = (size_t)g * DD + l * 4;
    const uint4* __restrict__ nrm4 = (const uint4*)g_nrm;
    const uint2* __restrict__ ekh2 = (const uint2*)ekhIn;

    uint4 hn = nrm4[(size_t)g * 16 + l];
    __half2 hgx = *(__half2*)&hn.x, hgy = *(__half2*)&hn.y;
    __half2 hix = *(__half2*)&hn.z, hiy = *(__half2*)&hn.w;
    float ng = g_normg[g], ni = g_normi[g];

    float4 AG = make_float4(0.f, 0.f, 0.f, 0.f);
    float4 AI = make_float4(0.f, 0.f, 0.f, 0.f);
    float rsg = 0.f, rsi = 0.f;

    int s = g_rowptr[g], e = g_rowptr[g + 1];
    int p = s;
    for (; p + 3 < e; p += 4) {
        int ta = __ldg(&g_edge[p].x);
        int tb = __ldg(&g_edge[p + 1].x);
        int tc = __ldg(&g_edge[p + 2].x);
        int td = __ldg(&g_edge[p + 3].x);
        uint4 na = nrm4[(size_t)ta * 16 + l];
        uint4 nb = nrm4[(size_t)tb * 16 + l];
        uint4 nc = nrm4[(size_t)tc * 16 + l];
        uint4 nd = nrm4[(size_t)td * 16 + l];
        uint2 ea = ekh2[(size_t)ta * 16 + l];
        uint2 eb = ekh2[(size_t)tb * 16 + l];
        uint2 ec = ekh2[(size_t)tc * 16 + l];
        uint2 ed = ekh2[(size_t)td * 16 + l];

        __half2 dda, ddb, ddc, ddd;
        EDGE_DOT_P(na, dda);
        EDGE_DOT_P(nb, ddb);
        EDGE_DOT_P(nc, ddc);
        EDGE_DOT_P(nd, ddd);
#pragma unroll
        for (int o = 8; o > 0; o >>= 1) {
            H2SHFL(dda, o);
            H2SHFL(ddb, o);
            H2SHFL(ddc, o);
            H2SHFL(ddd, o);
        }
        float2 dfa = __half22float2(dda);
        float2 dfb = __half22float2(ddb);
        float2 dfc = __half22float2(ddc);
        float2 dfd = __half22float2(ddd);
        float aga = (dfa.x + 1.f) * 0.5f, aia = (dfa.y + 1.f) * 0.5f;
        float agb = (dfb.x + 1.f) * 0.5f, aib = (dfb.y + 1.f) * 0.5f;
        float agc = (dfc.x + 1.f) * 0.5f, aic = (dfc.y + 1.f) * 0.5f;
        float agd = (dfd.x + 1.f) * 0.5f, aid = (dfd.y + 1.f) * 0.5f;
        EDGE_ACC(ea, aga, aia);
        EDGE_ACC(eb, agb, aib);
        EDGE_ACC(ec, agc, aic);
        EDGE_ACC(ed, agd, aid);
    }
    for (; p < e; p++) {
        int ta = __ldg(&g_edge[p].x);
        uint4 na = nrm4[(size_t)ta * 16 + l];
        uint2 ea = ekh2[(size_t)ta * 16 + l];
        __half2 dda;
        EDGE_DOT_P(na, dda);
#pragma unroll
        for (int o = 8; o > 0; o >>= 1) H2SHFL(dda, o);
        float2 dfa = __half22float2(dda);
        float aga = (dfa.x + 1.f) * 0.5f, aia = (dfa.y + 1.f) * 0.5f;
        EDGE_ACC(ea, aga, aia);
    }
    float dg_inv = rsg > 0.f ? 1.f / rsg : 0.f;
    float di_inv = rsi > 0.f ? 1.f / rsi : 0.f;
    float4 gv = make_float4(AG.x * dg_inv, AG.y * dg_inv, AG.z * dg_inv, AG.w * dg_inv);
    float4 iv = make_float4(AI.x * di_inv, AI.y * di_inv, AI.z * di_inv, AI.w * di_inv);
    __stcs((float4*)(gaa + ro), gv);     // write-once: streaming
    __stcs((float4*)(iaa + ro), iv);

    // combine: e_{l+1} = gnn + intl + gaa + iaa + ek
    // gnn/itl rows reconstructed from registers: |gnn|·ĝ, |itl|·î
    float2 hg01 = __half22float2(hgx), hg23 = __half22float2(hgy);
    float2 hi01 = __half22float2(hix), hi23 = __half22float2(hiy);
    uint2 ekc = ekh2[(size_t)g * 16 + l];
    float2 ek01 = __half22float2(*(__half2*)&ekc.x);
    float2 ek23 = __half22float2(*(__half2*)&ekc.y);
    float4 en;
    en.x = fmaf(ng, hg01.x, fmaf(ni, hi01.x, gv.x + iv.x + ek01.x));
    en.y = fmaf(ng, hg01.y, fmaf(ni, hi01.y, gv.y + iv.y + ek01.y));
    en.z = fmaf(ng, hg23.x, fmaf(ni, hi23.x, gv.z + iv.z + ek23.x));
    en.w = fmaf(ng, hg23.y, fmaf(ni, hi23.y, gv.w + iv.w + ek23.y));
    if (finalOut) {
        // final = e0 + e1 + e2 ; e0 lives in g_ekhA, e1 = ekhIn (=g_ekhB)
        uint2 e0c = ((const uint2*)g_ekhA)[(size_t)g * 16 + l];
        float2 z01 = __half22float2(*(__half2*)&e0c.x);
        float2 z23 = __half22float2(*(__half2*)&e0c.y);
        float4 ac;
        ac.x = z01.x + ek01.x + en.x;
        ac.y = z01.y + ek01.y + en.y;
        ac.z = z23.x + ek23.x + en.z;
        ac.w = z23.y + ek23.y + en.w;
        __stcs((float4*)(finalOut + ro), ac);   // write-once: streaming
    } else {
        __half2 h0 = __floats2half2_rn(en.x, en.y);
        __half2 h1 = __floats2half2_rn(en.z, en.w);
        uint2 u; u.x = *(unsigned*)&h0; u.y = *(unsigned*)&h1;
        ((uint2*)ekhOut)[(size_t)g * 16 + l] = u;   // hot: default policy
    }
}

// ---------------- launch ----------------
extern "C" void kernel_launch(void* const* d_in, const int* in_sizes, int n_in,
                              void* d_out, int out_size) {
    const float* user_emb = (const float*)d_in[0];
    const float* item_emb = (const float*)d_in[1];
    const float* Wu       = (const float*)d_in[2];
    const float* Wi       = (const float*)d_in[3];
    const float* adj      = (const float*)d_in[4];
    const int*   h        = (const int*)d_in[5];
    const int*   t        = (const int*)d_in[6];
    (void)in_sizes; (void)n_in; (void)out_size;

    float* out = (float*)d_out;
    const size_t ND = (size_t)NN * DD;
    float* out_ua  = out;                    // [N*D] = ua | ia
    float* out_gnn = out + ND;               // [L][N][D]
    float* out_int = out_gnn + (size_t)LL * ND;
    float* out_gaa = out_int + (size_t)LL * ND;
    float* out_iaa = out_gaa + (size_t)LL * ND;

    cudaFuncSetAttribute(phase1_kernel, cudaFuncAttributeMaxDynamicSharedMemorySize, IT_SMEM_BYTES);

    const int TPB = 256;
    const int SCAN_NB = (NN + 1023) / 1024;  // 147
    init_hist_kernel<<<NB_INIT + NB_HIST, TPB>>>((const float4*)user_emb,
                                                 (const float4*)item_emb,
                                                 (const int4*)h);
    reduce_scan_kernel<<<SCAN_NB, 1024>>>();
    apply_scan_kernel<<<SCAN_NB, 1024>>>();
    scatter_kernel<<<(EE / 8 + TPB - 1) / TPB, TPB>>>((const int4*)h, (const int4*)t,
                                                      (const float4*)adj);

    const int NODE_BLOCKS = NN * 16 / TPB;   // 9375
    for (int l = 0; l < LL; l++) {
        float* gnn = out_gnn + (size_t)l * ND;
        float* itl = out_int + (size_t)l * ND;
        float* gaa = out_gaa + (size_t)l * ND;
        float* iaa = out_iaa + (size_t)l * ND;

        phase1_kernel<<<NB_I + NB_SP, TPB, IT_SMEM_BYTES>>>(l, Wu, Wi, gnn, itl);
        fused_alpha_kernel<<<NODE_BLOCKS, TPB>>>(l, gaa, iaa,
                                                 (l == LL - 1) ? out_ua : nullptr);
    }
}